// round 3
// baseline (speedup 1.0000x reference)
#include <cuda_runtime.h>
#include <cuda_bf16.h>
#include <cstdint>
#include <cstddef>

using bf16 = __nv_bfloat16;

static constexpr int S = 4096, D = 1024, H = 2048;
static constexpr size_t NSD = (size_t)S * D;
static constexpr size_t NSH = (size_t)S * H;
static constexpr size_t NSS = (size_t)S * S;
static constexpr size_t NDH = (size_t)D * H;

// ===================== helpers (sm_80-era PTX only — compute_100-safe) =====
__device__ __forceinline__ uint32_t tl_smem_u32(const void* p) {
    uint32_t a;
    asm("{ .reg .u64 t; cvta.to.shared.u64 t, %1; cvt.u32.u64 %0, t; }" : "=r"(a) : "l"(p));
    return a;
}

// ldmatrix x4 for A tile (row-major [M][K], 80B row stride).
// Gives a-frags for one m16 tile at rows am0..am0+15, k bytes ksb..ksb+31.
__device__ __forceinline__ void tl_ldmA(uint32_t base, int am0, int ksb, int lane, uint32_t* a) {
    const uint32_t addr = base +
        (uint32_t)((am0 + (lane & 7) + ((lane >> 3) & 1) * 8) * 80 + ksb + (lane >> 4) * 16);
    asm volatile("ldmatrix.sync.aligned.m8n8.x4.shared.b16 {%0,%1,%2,%3}, [%4];"
                 : "=r"(a[0]), "=r"(a[1]), "=r"(a[2]), "=r"(a[3]) : "r"(addr));
}
// ldmatrix x4 for B tile ([N][K] row-major): covers n-tiles nb..nb+7 and nb+8..15.
// regs: {b0,b1} of n-tile nb, {b0,b1} of n-tile nb+8.
__device__ __forceinline__ void tl_ldmB(uint32_t base, int nb, int ksb, int lane, uint32_t* b) {
    const uint32_t addr = base +
        (uint32_t)((nb + (lane & 7) + ((lane >> 4) << 3)) * 80 + ksb + ((lane >> 3) & 1) * 16);
    asm volatile("ldmatrix.sync.aligned.m8n8.x4.shared.b16 {%0,%1,%2,%3}, [%4];"
                 : "=r"(b[0]), "=r"(b[1]), "=r"(b[2]), "=r"(b[3]) : "r"(addr));
}
__device__ __forceinline__ void tl_mma(float* c, const uint32_t* a, uint32_t b0, uint32_t b1) {
    asm volatile(
        "mma.sync.aligned.m16n8k16.row.col.f32.bf16.bf16.f32 "
        "{%0,%1,%2,%3}, {%4,%5,%6,%7}, {%8,%9}, {%0,%1,%2,%3};"
        : "+f"(c[0]), "+f"(c[1]), "+f"(c[2]), "+f"(c[3])
        : "r"(a[0]), "r"(a[1]), "r"(a[2]), "r"(a[3]), "r"(b0), "r"(b1));
}

// Fill one 4-tile stage (Ah,Al,Bh,Bl — each 128 rows x 32 bf16, 80B stride)
// with cp.async; commits a group. g* already point at (row0, k0).
__device__ __forceinline__ void tl_fill(uint32_t smdst,
                                        const bf16* g0, const bf16* g1,
                                        const bf16* g2, const bf16* g3,
                                        int lda, int ldb, int tid) {
#pragma unroll
    for (int i = 0; i < 8; i++) {
        const int idx = tid + i * 256;         // 0..2047
        const int tile = idx >> 9;             // 512 chunks per tile
        const int rem = idx & 511;
        const int r = rem >> 2, ch = rem & 3;  // row, 16B chunk
        const bf16* src;
        int ld;
        if (tile == 0)      { src = g0; ld = lda; }
        else if (tile == 1) { src = g1; ld = lda; }
        else if (tile == 2) { src = g2; ld = ldb; }
        else                { src = g3; ld = ldb; }
        const bf16* gp = src + (size_t)r * ld + ch * 8;
        const uint32_t dst = smdst + (uint32_t)(tile * 10240 + r * 80 + ch * 16);
        asm volatile("cp.async.cg.shared.global [%0], [%1], 16;" :: "r"(dst), "l"(gp));
    }
    asm volatile("cp.async.commit_group;" ::: "memory");
}

// ===================== scratch ============================================
struct alignas(256) TlScratch {
    bf16 xh[NSD], xl[NSD];
    bf16 wqt_h[NDH], wqt_l[NDH], wkt_h[NDH], wkt_l[NDH], wvt_h[NDH], wvt_l[NDH];
    bf16 wot_h[NDH], wot_l[NDH], w1t_h[NDH], w1t_l[NDH], w2t_h[NDH], w2t_l[NDH];
    bf16 qh[NSH], ql[NSH], kh[NSH], kl[NSH];
    bf16 vh[NSH], vl[NSH], vth[NSH], vtl[NSH];
    bf16 ah[NSS], al[NSS];
    bf16 aoh[NSH], aol[NSH];
    bf16 rh[NSD], rl[NSD];
    bf16 hh[NSH], hl[NSH];
    float scores[NSS];
    float resid[NSD];
};
__device__ TlScratch g_s;

// ===================== GEMM: C[M,N] = A[M,K] @ B[N,K]^T (bf16x3, HMMA) ====
// 128x128 CTA tile, K-tile 32, 2-stage cp.async pipeline, 2 CTAs/SM.
// EPI: 0 bias+split | 1 f32 | 2 split | 3 bias+add+f32+split | 4 relu+split | 5 bias+add+f32
// causal: 0 none | 1 skip n0>m0 | 2 clamp K to m0+128
static constexpr int TL_STAGE_B = 4 * 10240;              // 40960
static constexpr int TL_SMEM_TOTAL = 2 * TL_STAGE_B;      // 81920

template <int EPI>
__global__ __launch_bounds__(256, 2)
void tl_gemm(const bf16* __restrict__ Ah, const bf16* __restrict__ Al, int lda,
             const bf16* __restrict__ Bh, const bf16* __restrict__ Bl, int ldb,
             int Ktot, int causal,
             float* __restrict__ outf, bf16* __restrict__ outh, bf16* __restrict__ outl,
             const float* __restrict__ bias, const float* __restrict__ addsrc,
             int out_stride) {
    extern __shared__ char smem[];
    const int tid = threadIdx.x;
    const int lane = tid & 31;
    const int wid = tid >> 5;
    const int m0 = blockIdx.y * 128;
    const int n0 = blockIdx.x * 128;

    if (causal == 1 && n0 > m0) return;

    int KT = Ktot >> 5;
    if (causal == 2) {
        const int need = (m0 >> 5) + 4;
        KT = (need < KT) ? need : KT;
    }

    const int wm0 = (wid & 3) * 32;   // warp row offset in tile
    const int wn0 = (wid >> 2) * 64;  // warp col offset in tile
    const uint32_t smb = tl_smem_u32(smem);

    const bf16* pa_h = Ah + (size_t)m0 * lda;
    const bf16* pa_l = Al + (size_t)m0 * lda;
    const bf16* pb_h = Bh + (size_t)n0 * ldb;
    const bf16* pb_l = Bl + (size_t)n0 * ldb;

    float acc[2][8][4];
#pragma unroll
    for (int mt = 0; mt < 2; mt++)
#pragma unroll
        for (int nt = 0; nt < 8; nt++)
#pragma unroll
            for (int j = 0; j < 4; j++) acc[mt][nt][j] = 0.f;

    tl_fill(smb, pa_h, pa_l, pb_h, pb_l, lda, ldb, tid);  // stage 0, k0=0

    for (int kt = 0; kt < KT; kt++) {
        if (kt + 1 < KT) {
            const int k1 = (kt + 1) << 5;
            tl_fill(smb + ((kt + 1) & 1) * TL_STAGE_B,
                    pa_h + k1, pa_l + k1, pb_h + k1, pb_l + k1, lda, ldb, tid);
            asm volatile("cp.async.wait_group 1;" ::: "memory");
        } else {
            asm volatile("cp.async.wait_group 0;" ::: "memory");
        }
        __syncthreads();

        const uint32_t st = smb + (kt & 1) * TL_STAGE_B;
#pragma unroll
        for (int asel = 0; asel < 2; asel++) {            // 0: Ah, 1: Al
            const uint32_t abase = st + asel * 10240;
            const int nbsel = (asel == 0) ? 2 : 1;        // Ah x {Bh,Bl}; Al x {Bh}
#pragma unroll
            for (int ks = 0; ks < 2; ks++) {              // two k16 steps
                uint32_t af[2][4];
                tl_ldmA(abase, wm0, ks * 32, lane, af[0]);
                tl_ldmA(abase, wm0 + 16, ks * 32, lane, af[1]);
#pragma unroll
                for (int bsel = 0; bsel < 2; bsel++) {
                    if (bsel >= nbsel) break;
                    const uint32_t bbase = st + 20480 + bsel * 10240;
                    uint32_t bf[4][4];
#pragma unroll
                    for (int g = 0; g < 4; g++) tl_ldmB(bbase, wn0 + g * 16, ks * 32, lane, bf[g]);
#pragma unroll
                    for (int mt = 0; mt < 2; mt++)
#pragma unroll
                        for (int nt = 0; nt < 8; nt++)
                            tl_mma(acc[mt][nt], af[mt],
                                   bf[nt >> 1][(nt & 1) * 2], bf[nt >> 1][(nt & 1) * 2 + 1]);
                }
            }
        }
        __syncthreads();
    }

    // ---- epilogue (register-resident accumulators) ----
#pragma unroll
    for (int mt = 0; mt < 2; mt++)
#pragma unroll
        for (int nt = 0; nt < 8; nt++) {
            const int rbase = m0 + wm0 + mt * 16 + (lane >> 2);
            const int cn = n0 + wn0 + nt * 8 + (lane & 3) * 2;
#pragma unroll
            for (int h = 0; h < 2; h++) {
                const int m = rbase + h * 8;
                float v0 = acc[mt][nt][h * 2];
                float v1 = acc[mt][nt][h * 2 + 1];
                const size_t ob = (size_t)m * out_stride + cn;
                if (EPI == 1) {
                    *(float2*)(outf + ob) = make_float2(v0, v1);
                } else {
                    if (EPI == 0 || EPI == 4) { v0 += bias[cn]; v1 += bias[cn + 1]; }
                    if (EPI == 4) { v0 = fmaxf(v0, 0.f); v1 = fmaxf(v1, 0.f); }
                    if (EPI == 3 || EPI == 5) {
                        v0 += bias[cn] + addsrc[ob];
                        v1 += bias[cn + 1] + addsrc[ob + 1];
                        *(float2*)(outf + ob) = make_float2(v0, v1);
                    }
                    if (EPI != 5) {
                        const bf16 h0 = __float2bfloat16(v0);
                        const bf16 h1 = __float2bfloat16(v1);
                        *(__nv_bfloat162*)(outh + ob) = __halves2bfloat162(h0, h1);
                        *(__nv_bfloat162*)(outl + ob) = __halves2bfloat162(
                            __float2bfloat16(v0 - __bfloat162float(h0)),
                            __float2bfloat16(v1 - __bfloat162float(h1)));
                    }
                }
            }
        }
}

// ===================== support kernels =====================================
__global__ void tl_split_f32(const float* __restrict__ in, bf16* __restrict__ oh,
                             bf16* __restrict__ ol, int n) {
    const int i = blockIdx.x * blockDim.x + threadIdx.x;
    if (i < n) {
        const float v = in[i];
        const bf16 h = __float2bfloat16(v);
        oh[i] = h;
        ol[i] = __float2bfloat16(v - __bfloat162float(h));
    }
}

// in [R][C] f32 -> out [C][R] hi/lo bf16.  grid (C/32, R/32), block (32,8)
__global__ void tl_transpose_split(const float* __restrict__ in, bf16* __restrict__ oh,
                                   bf16* __restrict__ ol, int R, int C) {
    __shared__ float t[32][33];
    const int c0 = blockIdx.x * 32, r0 = blockIdx.y * 32;
    const int tx = threadIdx.x, ty = threadIdx.y;
#pragma unroll
    for (int i = 0; i < 32; i += 8)
        t[ty + i][tx] = in[(size_t)(r0 + ty + i) * C + c0 + tx];
    __syncthreads();
#pragma unroll
    for (int i = 0; i < 32; i += 8) {
        const float v = t[tx][ty + i];
        const size_t o = (size_t)(c0 + ty + i) * R + r0 + tx;
        const bf16 h = __float2bfloat16(v);
        oh[o] = h;
        ol[o] = __float2bfloat16(v - __bfloat162float(h));
    }
}

// in [R][C] bf16 -> out [C][R].  grid (C/32, R/32), block (32,8)
__global__ void tl_transpose_bf16(const bf16* __restrict__ in, bf16* __restrict__ out,
                                  int R, int C) {
    __shared__ bf16 t[32][33];
    const int c0 = blockIdx.x * 32, r0 = blockIdx.y * 32;
    const int tx = threadIdx.x, ty = threadIdx.y;
#pragma unroll
    for (int i = 0; i < 32; i += 8)
        t[ty + i][tx] = in[(size_t)(r0 + ty + i) * C + c0 + tx];
    __syncthreads();
#pragma unroll
    for (int i = 0; i < 32; i += 8)
        out[(size_t)(c0 + ty + i) * R + r0 + tx] = t[tx][ty + i];
}

// Row-wise causal softmax; writes fp32 attn (zeros above diag) + hi/lo split.
__global__ void tl_softmax(const float* __restrict__ scores, float* __restrict__ attn,
                           bf16* __restrict__ ah, bf16* __restrict__ al) {
    const int row = blockIdx.x;
    const int tid = threadIdx.x;  // 256
    const int nvalid = row + 1;
    const float scale = 0.02209708691207961f;  // 1/sqrt(2048)
    const float* srow = scores + (size_t)row * S;
    __shared__ float red[8];

    float v[16];
    float mx = -1e30f;
#pragma unroll
    for (int t = 0; t < 16; t++) {
        const int j = tid + t * 256;
        const float x = (j < nvalid) ? srow[j] * scale : -1e30f;
        v[t] = x;
        mx = fmaxf(mx, x);
    }
#pragma unroll
    for (int o = 16; o; o >>= 1) mx = fmaxf(mx, __shfl_xor_sync(0xffffffffu, mx, o));
    if ((tid & 31) == 0) red[tid >> 5] = mx;
    __syncthreads();
    float rmax = red[0];
#pragma unroll
    for (int i = 1; i < 8; i++) rmax = fmaxf(rmax, red[i]);
    __syncthreads();

    float sum = 0.f;
#pragma unroll
    for (int t = 0; t < 16; t++) {
        const int j = tid + t * 256;
        const float e = (j < nvalid) ? __expf(v[t] - rmax) : 0.f;
        v[t] = e;
        sum += e;
    }
#pragma unroll
    for (int o = 16; o; o >>= 1) sum += __shfl_xor_sync(0xffffffffu, sum, o);
    if ((tid & 31) == 0) red[tid >> 5] = sum;
    __syncthreads();
    float tot = 0.f;
#pragma unroll
    for (int i = 0; i < 8; i++) tot += red[i];
    const float inv = 1.f / tot;

#pragma unroll
    for (int t = 0; t < 16; t++) {
        const int j = tid + t * 256;
        const float p = v[t] * inv;
        const size_t o = (size_t)row * S + j;
        attn[o] = p;
        const bf16 h = __float2bfloat16(p);
        ah[o] = h;
        al[o] = __float2bfloat16(p - __bfloat162float(h));
    }
}

// ===================== host launch =========================================
extern "C" void kernel_launch(void* const* d_in, const int* in_sizes, int n_in,
                              void* d_out, int out_size) {
    const float* x  = (const float*)d_in[0];
    const float* Wq = (const float*)d_in[1];
    const float* bq = (const float*)d_in[2];
    const float* Wk = (const float*)d_in[3];
    const float* bk = (const float*)d_in[4];
    const float* Wv = (const float*)d_in[5];
    const float* bv = (const float*)d_in[6];
    const float* Wo = (const float*)d_in[7];
    const float* bo = (const float*)d_in[8];
    const float* W1 = (const float*)d_in[9];
    const float* b1 = (const float*)d_in[10];
    const float* W2 = (const float*)d_in[11];
    const float* b2 = (const float*)d_in[12];
    float* out  = (float*)d_out;        // [S,D]
    float* attn = out + NSD;            // [S,S]

    TlScratch* s = nullptr;
    cudaGetSymbolAddress((void**)&s, g_s);

    cudaFuncSetAttribute(tl_gemm<0>, cudaFuncAttributeMaxDynamicSharedMemorySize, TL_SMEM_TOTAL);
    cudaFuncSetAttribute(tl_gemm<1>, cudaFuncAttributeMaxDynamicSharedMemorySize, TL_SMEM_TOTAL);
    cudaFuncSetAttribute(tl_gemm<2>, cudaFuncAttributeMaxDynamicSharedMemorySize, TL_SMEM_TOTAL);
    cudaFuncSetAttribute(tl_gemm<3>, cudaFuncAttributeMaxDynamicSharedMemorySize, TL_SMEM_TOTAL);
    cudaFuncSetAttribute(tl_gemm<4>, cudaFuncAttributeMaxDynamicSharedMemorySize, TL_SMEM_TOTAL);
    cudaFuncSetAttribute(tl_gemm<5>, cudaFuncAttributeMaxDynamicSharedMemorySize, TL_SMEM_TOTAL);

    const dim3 tt(32, 8);
    tl_split_f32<<<(int)((NSD + 255) / 256), 256>>>(x, s->xh, s->xl, (int)NSD);
    tl_transpose_split<<<dim3(H / 32, D / 32), tt>>>(Wq, s->wqt_h, s->wqt_l, D, H);
    tl_transpose_split<<<dim3(H / 32, D / 32), tt>>>(Wk, s->wkt_h, s->wkt_l, D, H);
    tl_transpose_split<<<dim3(H / 32, D / 32), tt>>>(Wv, s->wvt_h, s->wvt_l, D, H);
    tl_transpose_split<<<dim3(D / 32, H / 32), tt>>>(Wo, s->wot_h, s->wot_l, H, D);
    tl_transpose_split<<<dim3(H / 32, D / 32), tt>>>(W1, s->w1t_h, s->w1t_l, D, H);
    tl_transpose_split<<<dim3(D / 32, H / 32), tt>>>(W2, s->w2t_h, s->w2t_l, H, D);

    const dim3 g_sh(H / 128, S / 128);   // [S,H] outputs
    const dim3 g_ss(S / 128, S / 128);   // [S,S]
    const dim3 g_sd(D / 128, S / 128);   // [S,D]

    // q, k, v = x @ W + b
    tl_gemm<0><<<g_sh, 256, TL_SMEM_TOTAL>>>(s->xh, s->xl, D, s->wqt_h, s->wqt_l, D,
                                             D, 0, nullptr, s->qh, s->ql, bq, nullptr, H);
    tl_gemm<0><<<g_sh, 256, TL_SMEM_TOTAL>>>(s->xh, s->xl, D, s->wkt_h, s->wkt_l, D,
                                             D, 0, nullptr, s->kh, s->kl, bk, nullptr, H);
    tl_gemm<0><<<g_sh, 256, TL_SMEM_TOTAL>>>(s->xh, s->xl, D, s->wvt_h, s->wvt_l, D,
                                             D, 0, nullptr, s->vh, s->vl, bv, nullptr, H);
    // v^T for attn@v
    tl_transpose_bf16<<<dim3(H / 32, S / 32), tt>>>(s->vh, s->vth, S, H);
    tl_transpose_bf16<<<dim3(H / 32, S / 32), tt>>>(s->vl, s->vtl, S, H);
    // scores = q @ k^T (causal tiles only; scale folded into softmax)
    tl_gemm<1><<<g_ss, 256, TL_SMEM_TOTAL>>>(s->qh, s->ql, H, s->kh, s->kl, H,
                                             H, 1, s->scores, nullptr, nullptr, nullptr, nullptr, S);
    tl_softmax<<<S, 256>>>(s->scores, attn, s->ah, s->al);
    // attn_out = attn @ v (K clamped to m0+128)
    tl_gemm<2><<<g_sh, 256, TL_SMEM_TOTAL>>>(s->ah, s->al, S, s->vth, s->vtl, S,
                                             S, 2, nullptr, s->aoh, s->aol, nullptr, nullptr, H);
    // resid = x + attn_out @ Wo + bo
    tl_gemm<3><<<g_sd, 256, TL_SMEM_TOTAL>>>(s->aoh, s->aol, H, s->wot_h, s->wot_l, H,
                                             H, 0, s->resid, s->rh, s->rl, bo, x, D);
    // hmid = relu(resid @ W1 + b1)
    tl_gemm<4><<<g_sh, 256, TL_SMEM_TOTAL>>>(s->rh, s->rl, D, s->w1t_h, s->w1t_l, D,
                                             D, 0, nullptr, s->hh, s->hl, b1, nullptr, H);
    // out = resid + hmid @ W2 + b2
    tl_gemm<5><<<g_sd, 256, TL_SMEM_TOTAL>>>(s->hh, s->hl, H, s->w2t_h, s->w2t_l, H,
                                             H, 0, out, nullptr, nullptr, b2, s->resid, D);
}